// round 13
// baseline (speedup 1.0000x reference)
#include <cuda_runtime.h>
#include <cuda_bf16.h>
#include <math.h>
#include <stdint.h>

// Problem constants
#define LL 2048
#define SS 2048
#define NB 2
#define HH 16
#define DD 64
#define EE 1024
#define BH 32          // NB*HH
#define MROWS 4096     // LL*NB

// ---------------------------------------------------------------------------
// Scratch (device globals; no allocation allowed)
// ---------------------------------------------------------------------------
__device__ __nv_bfloat16 g_qh[(size_t)BH * LL * DD];
__device__ __nv_bfloat16 g_ql[(size_t)BH * LL * DD];
__device__ __nv_bfloat16 g_kh[(size_t)BH * SS * DD];
__device__ __nv_bfloat16 g_kl[(size_t)BH * SS * DD];
__device__ __nv_bfloat16 g_vh[(size_t)BH * SS * DD];
__device__ __nv_bfloat16 g_vl[(size_t)BH * SS * DD];

__device__ __nv_bfloat16 g_a3h[3][(size_t)MROWS * EE];   // q/k/v input splits; [0] reused for attn out
__device__ __nv_bfloat16 g_a3l[3][(size_t)MROWS * EE];
__device__ __nv_bfloat16 g_w3h[4][(size_t)EE * EE];      // Wq, Wk, Wv, Wo transposed splits
__device__ __nv_bfloat16 g_w3l[4][(size_t)EE * EE];

// ---------------------------------------------------------------------------
// Common PTX helpers
// ---------------------------------------------------------------------------
__device__ __forceinline__ uint32_t smem_u32(const void* p) {
    uint32_t a;
    asm("{ .reg .u64 t; cvta.to.shared.u64 t, %1; cvt.u32.u64 %0, t; }"
        : "=r"(a) : "l"(p));
    return a;
}

__device__ __forceinline__ void ldmatrix4(uint32_t* r, uint32_t addr) {
    asm volatile("ldmatrix.sync.aligned.m8n8.x4.shared.b16 {%0,%1,%2,%3}, [%4];"
                 : "=r"(r[0]), "=r"(r[1]), "=r"(r[2]), "=r"(r[3]) : "r"(addr));
}

__device__ __forceinline__ void ldmatrix4t(uint32_t* r, uint32_t addr) {
    asm volatile("ldmatrix.sync.aligned.m8n8.x4.trans.shared.b16 {%0,%1,%2,%3}, [%4];"
                 : "=r"(r[0]), "=r"(r[1]), "=r"(r[2]), "=r"(r[3]) : "r"(addr));
}

__device__ __forceinline__ void mma16816(float* c, const uint32_t* a,
                                         uint32_t b0, uint32_t b1) {
    asm volatile("mma.sync.aligned.m16n8k16.row.col.f32.bf16.bf16.f32 "
                 "{%0,%1,%2,%3}, {%4,%5,%6,%7}, {%8,%9}, {%0,%1,%2,%3};"
                 : "+f"(c[0]), "+f"(c[1]), "+f"(c[2]), "+f"(c[3])
                 : "r"(a[0]), "r"(a[1]), "r"(a[2]), "r"(a[3]), "r"(b0), "r"(b1));
}

// pack two f32 -> bf16x2 (f0 in low half, f1 in high half), RN
__device__ __forceinline__ uint32_t pk_bf16x2(float f0, float f1) {
    uint32_t r;
    asm("cvt.rn.bf16x2.f32 %0, %2, %1;" : "=r"(r) : "f"(f0), "f"(f1));
    return r;
}

#define CP_ASYNC16(dst, src) \
    asm volatile("cp.async.cg.shared.global [%0], [%1], 16;" :: "r"(dst), "l"(src))
#define CP_COMMIT() asm volatile("cp.async.commit_group;" ::: "memory")
#define CP_WAIT1()  asm volatile("cp.async.wait_group 1;" ::: "memory")

// ---------------------------------------------------------------------------
// mma.sync GEMM: C[4096x1024] = X*W via bf16x3 split (K' = 3*1024)
// CTA 128x128, 8 warps (2m x 4n), warp tile 64x32, 3-stage cp.async, 2 CTA/SM.
// blockIdx.z selects the problem instance (merged Q/K/V launch).
// mode 0: fp32 row-major; 1: bf16 hi/lo head-major.
// ---------------------------------------------------------------------------
#define NSTAGE 3
#define NIT 48
#define STAGE_BYTES 32768
#define BOFF 16384
#define GSM_TOTAL (NSTAGE * STAGE_BYTES)

struct GemmArgs {
    const __nv_bfloat16 *ah, *al, *bth, *btl;
    __nv_bfloat16 *dsth, *dstl;
};
struct GemmArgs3 { GemmArgs g[3]; };

__device__ __forceinline__ void load_tile(int it, int buf, int tid, int m0, int n0,
                                          const __nv_bfloat16* __restrict__ Ah,
                                          const __nv_bfloat16* __restrict__ Al,
                                          const __nv_bfloat16* __restrict__ Bth,
                                          const __nv_bfloat16* __restrict__ Btl,
                                          uint32_t sb)
{
    const int term = it >> 4;
    const int kc = (it & 15) << 6;
    const __nv_bfloat16* As = (term == 1) ? Al : Ah;
    const __nv_bfloat16* Bs = (term == 2) ? Btl : Bth;
    const uint32_t abase = sb + buf * STAGE_BYTES;
    const uint32_t bbase = abase + BOFF;
#pragma unroll
    for (int i = 0; i < 8; i++) {
        int g = i * 256 + tid;
        int row = (g >> 3) & 127;
        int c = g & 7;
        const __nv_bfloat16* src;
        uint32_t dst;
        if (g < 1024) {
            src = As + (size_t)(m0 + row) * EE + kc + (c << 3);
            dst = abase + row * 128 + ((c ^ (row & 7)) << 4);
        } else {
            src = Bs + (size_t)(n0 + row) * EE + kc + (c << 3);
            dst = bbase + row * 128 + ((c ^ (row & 7)) << 4);
        }
        CP_ASYNC16(dst, src);
    }
}

__global__ void __launch_bounds__(256, 2) gemm_mma_bf16x3(
    GemmArgs3 A, float* __restrict__ dstf, int mode)
{
    extern __shared__ __align__(1024) char sm[];
    const uint32_t sb = smem_u32(sm);
    const GemmArgs ga = A.g[blockIdx.z];
    const __nv_bfloat16* __restrict__ Ah  = ga.ah;
    const __nv_bfloat16* __restrict__ Al  = ga.al;
    const __nv_bfloat16* __restrict__ Bth = ga.bth;
    const __nv_bfloat16* __restrict__ Btl = ga.btl;
    const int tid = threadIdx.x;
    const int wid = tid >> 5, lane = tid & 31;
    const int wm = wid >> 2;
    const int wn = wid & 3;
    const int m0 = blockIdx.y * 128;
    const int n0 = blockIdx.x * 128;

    float acc[4][4][4];
#pragma unroll
    for (int i = 0; i < 4; i++)
#pragma unroll
        for (int j = 0; j < 4; j++)
#pragma unroll
            for (int k = 0; k < 4; k++) acc[i][j][k] = 0.f;

    load_tile(0, 0, tid, m0, n0, Ah, Al, Bth, Btl, sb);
    CP_COMMIT();
    load_tile(1, 1, tid, m0, n0, Ah, Al, Bth, Btl, sb);
    CP_COMMIT();

    const int a_r = (lane & 7) + ((lane >> 3) & 1) * 8;
    const int a_c8 = lane >> 4;
    const int b_r = (lane & 7) + (lane >> 4) * 8;
    const int b_c8 = (lane >> 3) & 1;

    for (int it = 0; it < NIT; ++it) {
        CP_WAIT1();
        __syncthreads();
        if (it + 2 < NIT)
            load_tile(it + 2, (it + 2) % NSTAGE, tid, m0, n0, Ah, Al, Bth, Btl, sb);
        CP_COMMIT();

        const int buf = it % NSTAGE;
        const uint32_t Ab = sb + buf * STAGE_BYTES;
        const uint32_t Bb = Ab + BOFF;
#pragma unroll
        for (int ks = 0; ks < 4; ks++) {
            const int k0 = ks * 16;
            uint32_t a[4][4];
#pragma unroll
            for (int mt = 0; mt < 4; mt++) {
                int row = wm * 64 + mt * 16 + a_r;
                int col = k0 + 8 * a_c8;
                uint32_t addr = Ab + row * 128 + (((col >> 3) ^ (row & 7)) << 4);
                ldmatrix4(a[mt], addr);
            }
            uint32_t b[2][4];
#pragma unroll
            for (int bt = 0; bt < 2; bt++) {
                int row = wn * 32 + bt * 16 + b_r;
                int col = k0 + 8 * b_c8;
                uint32_t addr = Bb + row * 128 + (((col >> 3) ^ (row & 7)) << 4);
                ldmatrix4(b[bt], addr);
            }
#pragma unroll
            for (int mt = 0; mt < 4; mt++) {
#pragma unroll
                for (int nt = 0; nt < 4; nt++) {
                    uint32_t b0 = b[nt >> 1][(nt & 1) * 2];
                    uint32_t b1 = b[nt >> 1][(nt & 1) * 2 + 1];
                    mma16816(acc[mt][nt], a[mt], b0, b1);
                }
            }
        }
    }

    // Epilogue
#pragma unroll
    for (int mt = 0; mt < 4; mt++) {
#pragma unroll
        for (int nt = 0; nt < 4; nt++) {
            int m = m0 + wm * 64 + mt * 16 + (lane >> 2);
            int n = n0 + wn * 32 + nt * 8 + 2 * (lane & 3);
#pragma unroll
            for (int half = 0; half < 2; half++) {
                int mm = m + half * 8;
                float v0 = acc[mt][nt][half * 2];
                float v1 = acc[mt][nt][half * 2 + 1];
                if (mode == 0) {
                    *(float2*)&dstf[(size_t)mm * EE + n] = make_float2(v0, v1);
                } else {
                    int t = mm >> 1, nb = mm & 1;
                    int h = n >> 6, d = n & 63;
                    size_t idx = ((size_t)((nb * HH + h) * LL + t)) * DD + d;
                    uint32_t hv = pk_bf16x2(v0, v1);
                    float r0 = v0 - __uint_as_float(hv << 16);
                    float r1 = v1 - __uint_as_float(hv & 0xffff0000u);
                    uint32_t lv = pk_bf16x2(r0, r1);
                    *(uint32_t*)&ga.dsth[idx] = hv;
                    *(uint32_t*)&ga.dstl[idx] = lv;
                }
            }
        }
    }
}

// ---------------------------------------------------------------------------
// Conversion kernels (merged over blockIdx.z)
// ---------------------------------------------------------------------------
struct SplitArgs {
    const float* x[3];
    __nv_bfloat16 *h[3], *l[3];
};

__global__ void __launch_bounds__(256) split_kernel(SplitArgs S, int n4)
{
    int i = blockIdx.x * 256 + threadIdx.x;
    if (i >= n4) return;
    const int z = blockIdx.z;
    float4 v = ((const float4*)S.x[z])[i];
    uint32_t h0 = pk_bf16x2(v.x, v.y);
    uint32_t h1 = pk_bf16x2(v.z, v.w);
    float r0 = v.x - __uint_as_float(h0 << 16);
    float r1 = v.y - __uint_as_float(h0 & 0xffff0000u);
    float r2 = v.z - __uint_as_float(h1 << 16);
    float r3 = v.w - __uint_as_float(h1 & 0xffff0000u);
    uint32_t l0 = pk_bf16x2(r0, r1);
    uint32_t l1 = pk_bf16x2(r2, r3);
    *(uint2*)(S.h[z] + 4 * (size_t)i) = make_uint2(h0, h1);
    *(uint2*)(S.l[z] + 4 * (size_t)i) = make_uint2(l0, l1);
}

struct WArgs {
    const float* W[4];
    __nv_bfloat16 *th[4], *tl[4];
};

// W[k][n] -> Wt[n][k] bf16 hi/lo
__global__ void __launch_bounds__(256) wtrans_split(WArgs WA)
{
    __shared__ float t[32][33];
    const int z = blockIdx.z;
    const float* __restrict__ W = WA.W[z];
    const int n0 = blockIdx.x * 32, k0 = blockIdx.y * 32;
    const int tx = threadIdx.x & 31, ty = threadIdx.x >> 5;
#pragma unroll
    for (int j = 0; j < 32; j += 8)
        t[ty + j][tx] = W[(size_t)(k0 + ty + j) * EE + n0 + tx];
    __syncthreads();
#pragma unroll
    for (int j = 0; j < 32; j += 8) {
        float v = t[tx][ty + j];
        __nv_bfloat16 h = __float2bfloat16(v);
        __nv_bfloat16 l = __float2bfloat16(v - __bfloat162float(h));
        WA.th[z][(size_t)(n0 + ty + j) * EE + k0 + tx] = h;
        WA.tl[z][(size_t)(n0 + ty + j) * EE + k0 + tx] = l;
    }
}

// ---------------------------------------------------------------------------
// mma.sync flash attention, 512 threads / 16 warps per CTA.
// CTA: 128 q rows x full S sweep; warps: wm=wid>>1 (8 groups x 16 rows),
// wn=wid&1 (2 groups x 64 s-cols). Per warp: 16 rows x 64 s, accO=32 regs.
// QK: bf16x3; PV: bf16x3. No-max softmax. s-tile 128, depth-1 prefetch.
// smem: Qh 16K | Ql 16K | 2 stages x (Kh|Kl|Vh|Vl 64K) | lsum 1K
// ---------------------------------------------------------------------------
#define ASTG(b) (32768 + (b) * 65536)
#define ALS 163840
#define ASM_TOTAL (163840 + 1024)

__global__ void __launch_bounds__(512, 1) attn_mma(
    const __nv_bfloat16* __restrict__ Qh, const __nv_bfloat16* __restrict__ Ql,
    const __nv_bfloat16* __restrict__ Kh, const __nv_bfloat16* __restrict__ Kl,
    const __nv_bfloat16* __restrict__ Vh, const __nv_bfloat16* __restrict__ Vl,
    const float* __restrict__ prev,
    const unsigned char* __restrict__ am, const unsigned char* __restrict__ kpm,
    float* __restrict__ out_logits,
    __nv_bfloat16* __restrict__ oh, __nv_bfloat16* __restrict__ ol)
{
    extern __shared__ __align__(1024) char sm[];
    const uint32_t sb = smem_u32(sm);
    const int tid = threadIdx.x, wid = tid >> 5, lane = tid & 31;
    const int wm = wid >> 1, wn = wid & 1;
    const int bh = blockIdx.y, nb = bh >> 4, hh = bh & 15;
    const int q0 = blockIdx.x * 128;

    const int a_r = (lane & 7) + ((lane >> 3) & 1) * 8;
    const int a_c8 = lane >> 4;
    const int b_r = (lane & 7) + (lane >> 4) * 8;
    const int b_c8 = (lane >> 3) & 1;

    // Load Q (Qh then Ql): 2048 16B chunks, 512 threads
#pragma unroll
    for (int i = 0; i < 4; i++) {
        int g = i * 512 + tid;
        int arr = g >> 10, local = g & 1023;
        int row = local >> 3, c = local & 7;
        const __nv_bfloat16* src = (arr ? Ql : Qh) +
            ((size_t)bh * LL + q0 + row) * DD + (c << 3);
        uint32_t dst = sb + arr * 16384 + row * 128 + ((c ^ (row & 7)) << 4);
        CP_ASYNC16(dst, src);
    }
    // Stage 0 (Kh, Kl, Vh, Vl): 4096 chunks
#pragma unroll
    for (int i = 0; i < 8; i++) {
        int g = i * 512 + tid;
        int which = g >> 10, local = g & 1023;
        int row = local >> 3, c = local & 7;
        const __nv_bfloat16* base =
            (which == 0) ? Kh : (which == 1) ? Kl : (which == 2) ? Vh : Vl;
        const __nv_bfloat16* src = base + ((size_t)bh * SS + row) * DD + (c << 3);
        uint32_t dst = sb + ASTG(0) + which * 16384 + row * 128 + ((c ^ (row & 7)) << 4);
        CP_ASYNC16(dst, src);
    }
    CP_COMMIT();

    float accO[8][4];
#pragma unroll
    for (int j = 0; j < 8; j++)
#pragma unroll
        for (int k = 0; k < 4; k++) accO[j][k] = 0.f;
    float psum[2] = {0.f, 0.f};

    for (int it = 0; it < 16; ++it) {
        const int s0 = it * 128, buf = it & 1;
        if (it + 1 < 16) {
            const int nbuf = (it + 1) & 1, ns0 = (it + 1) * 128;
#pragma unroll
            for (int i = 0; i < 8; i++) {
                int g = i * 512 + tid;
                int which = g >> 10, local = g & 1023;
                int row = local >> 3, c = local & 7;
                const __nv_bfloat16* base =
                    (which == 0) ? Kh : (which == 1) ? Kl : (which == 2) ? Vh : Vl;
                const __nv_bfloat16* src = base +
                    ((size_t)bh * SS + ns0 + row) * DD + (c << 3);
                uint32_t dst = sb + ASTG(nbuf) + which * 16384 + row * 128 +
                               ((c ^ (row & 7)) << 4);
                CP_ASYNC16(dst, src);
            }
        }
        CP_COMMIT();
        CP_WAIT1();
        __syncthreads();

        const uint32_t KB = sb + ASTG(buf);
        const uint32_t VB  = KB + 32768;
        const uint32_t VLB = KB + 49152;

#pragma unroll
        for (int sh = 0; sh < 2; sh++) {        // 32-col half of this warp's 64
            // ---- S = Q K^T (3-term split), warp tile m16 x n32 ----
            float accS[4][4];
#pragma unroll
            for (int j = 0; j < 4; j++)
#pragma unroll
                for (int k = 0; k < 4; k++) accS[j][k] = 0.f;

#pragma unroll
            for (int kk = 0; kk < 12; kk++) {
                const int term = kk >> 2, kc = (kk & 3) * 16;
                const uint32_t Ab = sb + (term == 1 ? 16384 : 0);
                const uint32_t Bb = KB + (term == 2 ? 16384 : 0);
                uint32_t a[4];
                {
                    int row = wm * 16 + a_r;
                    int col = kc + 8 * a_c8;
                    ldmatrix4(a, Ab + row * 128 + (((col >> 3) ^ (row & 7)) << 4));
                }
                uint32_t b[2][4];
#pragma unroll
                for (int g = 0; g < 2; g++) {
                    int row = wn * 64 + sh * 32 + g * 16 + b_r;
                    int col = kc + 8 * b_c8;
                    ldmatrix4(b[g], Bb + row * 128 + (((col >> 3) ^ (row & 7)) << 4));
                }
#pragma unroll
                for (int nt = 0; nt < 4; nt++)
                    mma16816(accS[nt], a,
                             b[nt >> 1][(nt & 1) * 2], b[nt >> 1][(nt & 1) * 2 + 1]);
            }

            // ---- logits + exp + PV (3-term) per 16-wide k-slice ----
#pragma unroll
            for (int ks = 0; ks < 2; ks++) {
                uint32_t pA[4], pAl[4];
#pragma unroll
                for (int sub = 0; sub < 2; sub++) {
                    const int nt = 2 * ks + sub;
                    const int col = s0 + wn * 64 + sh * 32 + nt * 8 + 2 * (lane & 3);
                    uchar2 kv2 = *(const uchar2*)&kpm[(size_t)nb * SS + col];
#pragma unroll
                    for (int half = 0; half < 2; half++) {
                        const int row = q0 + wm * 16 + (lane >> 2) + half * 8;
                        size_t base = ((size_t)bh * LL + row) * SS + col;
                        float2 pv = *(const float2*)&prev[base];
                        uchar2 av2 = *(const uchar2*)&am[(size_t)row * SS + col];
                        float c0 = accS[nt][half * 2];
                        float c1 = accS[nt][half * 2 + 1];
                        float lg0 = (av2.x | kv2.x) ? -INFINITY : fmaf(c0, 0.125f, pv.x);
                        float lg1 = (av2.y | kv2.y) ? -INFINITY : fmaf(c1, 0.125f, pv.y);
                        *(float2*)&out_logits[base] = make_float2(lg0, lg1);
                        float p0 = __expf(lg0), p1 = __expf(lg1);
                        psum[half] += p0 + p1;
                        uint32_t ph = pk_bf16x2(p0, p1);
                        float r0 = p0 - __uint_as_float(ph << 16);
                        float r1 = p1 - __uint_as_float(ph & 0xffff0000u);
                        pA[sub * 2 + half]  = ph;
                        pAl[sub * 2 + half] = pk_bf16x2(r0, r1);
                    }
                }
                const int vrow = wn * 64 + sh * 32 + ks * 16 + a_r;
                uint32_t vb[4][4];
#pragma unroll
                for (int dg = 0; dg < 4; dg++) {
                    int chunk = dg * 2 + (lane >> 4);
                    ldmatrix4t(vb[dg], VB + vrow * 128 + ((chunk ^ (vrow & 7)) << 4));
                }
#pragma unroll
                for (int dn = 0; dn < 8; dn++) {
                    uint32_t b0 = vb[dn >> 1][(dn & 1) * 2];
                    uint32_t b1 = vb[dn >> 1][(dn & 1) * 2 + 1];
                    mma16816(accO[dn], pA, b0, b1);
                    mma16816(accO[dn], pAl, b0, b1);
                }
                uint32_t vbl[4][4];
#pragma unroll
                for (int dg = 0; dg < 4; dg++) {
                    int chunk = dg * 2 + (lane >> 4);
                    ldmatrix4t(vbl[dg], VLB + vrow * 128 + ((chunk ^ (vrow & 7)) << 4));
                }
#pragma unroll
                for (int dn = 0; dn < 8; dn++)
                    mma16816(accO[dn], pA,
                             vbl[dn >> 1][(dn & 1) * 2], vbl[dn >> 1][(dn & 1) * 2 + 1]);
            }
        }
        __syncthreads();
    }

    // ---- epilogue: row-sum reduce, cross-warp (wn) O sum, normalize, write ----
    float* ls = (float*)(sm + ALS);
#pragma unroll
    for (int half = 0; half < 2; half++) {
        float v = psum[half];
        v += __shfl_xor_sync(0xffffffffu, v, 1);
        v += __shfl_xor_sync(0xffffffffu, v, 2);
        int row = wm * 16 + half * 8 + (lane >> 2);
        if ((lane & 3) == 0) ls[wn * 128 + row] = v;
    }
    __syncthreads();
    float* ob = (float*)(sm + 32768);      // reuse stage0 (32KB): 128 x 64 f32
    if (wn == 1) {
#pragma unroll
        for (int dn = 0; dn < 8; dn++) {
            int rl = wm * 16 + (lane >> 2);
            int col = dn * 8 + 2 * (lane & 3);
            *(float2*)&ob[rl * 64 + col] = make_float2(accO[dn][0], accO[dn][1]);
            *(float2*)&ob[(rl + 8) * 64 + col] = make_float2(accO[dn][2], accO[dn][3]);
        }
    }
    __syncthreads();
    if (wn == 0) {
#pragma unroll
        for (int dn = 0; dn < 8; dn++)
#pragma unroll
            for (int half = 0; half < 2; half++) {
                int rl = wm * 16 + (lane >> 2) + half * 8;
                int col = dn * 8 + 2 * (lane & 3);
                float2 o2 = *(float2*)&ob[rl * 64 + col];
                float inv = 1.f / (ls[rl] + ls[128 + rl]);
                float o0 = (accO[dn][half * 2] + o2.x) * inv;
                float o1 = (accO[dn][half * 2 + 1] + o2.y) * inv;
                size_t r = (size_t)(q0 + rl) * NB + nb;
                size_t cg = (size_t)hh * 64 + col;
                uint32_t hv = pk_bf16x2(o0, o1);
                float r0 = o0 - __uint_as_float(hv << 16);
                float r1 = o1 - __uint_as_float(hv & 0xffff0000u);
                uint32_t lv = pk_bf16x2(r0, r1);
                *(uint32_t*)&oh[r * EE + cg] = hv;
                *(uint32_t*)&ol[r * EE + cg] = lv;
            }
    }
}

// ---------------------------------------------------------------------------
extern "C" void kernel_launch(void* const* d_in, const int* in_sizes, int n_in,
                              void* d_out, int out_size)
{
    const float* query = (const float*)d_in[0];
    const float* key   = (const float*)d_in[1];
    const float* value = (const float*)d_in[2];
    const float* prev  = (const float*)d_in[3];
    const unsigned char* kpm = (const unsigned char*)d_in[4];
    const unsigned char* am  = (const unsigned char*)d_in[5];
    const float* Wq = (const float*)d_in[6];
    const float* Wk = (const float*)d_in[7];
    const float* Wv = (const float*)d_in[8];
    const float* Wo = (const float*)d_in[9];

    float* out = (float*)d_out;
    float* out_logits = out + (size_t)LL * NB * EE;

    __nv_bfloat16 *qh, *ql, *kh, *kl, *vh, *vl;
    __nv_bfloat16 *a3h, *a3l, *w3h, *w3l;
    cudaGetSymbolAddress((void**)&qh, g_qh);
    cudaGetSymbolAddress((void**)&ql, g_ql);
    cudaGetSymbolAddress((void**)&kh, g_kh);
    cudaGetSymbolAddress((void**)&kl, g_kl);
    cudaGetSymbolAddress((void**)&vh, g_vh);
    cudaGetSymbolAddress((void**)&vl, g_vl);
    cudaGetSymbolAddress((void**)&a3h, g_a3h);
    cudaGetSymbolAddress((void**)&a3l, g_a3l);
    cudaGetSymbolAddress((void**)&w3h, g_w3h);
    cudaGetSymbolAddress((void**)&w3l, g_w3l);

    const size_t ASZ = (size_t)MROWS * EE;
    const size_t WSZ = (size_t)EE * EE;

    cudaFuncSetAttribute(gemm_mma_bf16x3,
                         cudaFuncAttributeMaxDynamicSharedMemorySize, GSM_TOTAL);
    cudaFuncSetAttribute(attn_mma,
                         cudaFuncAttributeMaxDynamicSharedMemorySize, ASM_TOTAL);

    const int nsplit4 = MROWS * EE / 4;

    // 1) Transpose+split all 4 weight matrices (z = 4)
    WArgs wa;
    wa.W[0] = Wq; wa.W[1] = Wk; wa.W[2] = Wv; wa.W[3] = Wo;
    for (int z = 0; z < 4; z++) { wa.th[z] = w3h + z * WSZ; wa.tl[z] = w3l + z * WSZ; }
    wtrans_split<<<dim3(EE / 32, EE / 32, 4), 256>>>(wa);

    // 2) Split all 3 inputs (z = 3)
    SplitArgs sa;
    sa.x[0] = query; sa.x[1] = key; sa.x[2] = value;
    for (int z = 0; z < 3; z++) { sa.h[z] = a3h + z * ASZ; sa.l[z] = a3l + z * ASZ; }
    split_kernel<<<dim3((nsplit4 + 255) / 256, 1, 3), 256>>>(sa, nsplit4);

    // 3) Q/K/V projections in one launch (z = 3), bf16 hi/lo head-major out
    GemmArgs3 g3;
    __nv_bfloat16* dh[3] = {qh, kh, vh};
    __nv_bfloat16* dl[3] = {ql, kl, vl};
    for (int z = 0; z < 3; z++) {
        g3.g[z].ah = a3h + z * ASZ;  g3.g[z].al = a3l + z * ASZ;
        g3.g[z].bth = w3h + z * WSZ; g3.g[z].btl = w3l + z * WSZ;
        g3.g[z].dsth = dh[z];        g3.g[z].dstl = dl[z];
    }
    gemm_mma_bf16x3<<<dim3(EE / 128, MROWS / 128, 3), 256, GSM_TOTAL>>>(g3, nullptr, 1);

    // 4) Attention (writes logits + attn-out split into a3h[0]/a3l[0])
    attn_mma<<<dim3(LL / 128, BH), 512, ASM_TOTAL>>>(qh, ql, kh, kl, vh, vl,
                                                     prev, am, kpm,
                                                     out_logits, a3h, a3l);

    // 5) Output projection (fp32 row-major)
    GemmArgs3 go3;
    go3.g[0].ah = a3h;               go3.g[0].al = a3l;
    go3.g[0].bth = w3h + 3 * WSZ;    go3.g[0].btl = w3l + 3 * WSZ;
    go3.g[0].dsth = nullptr;         go3.g[0].dstl = nullptr;
    go3.g[1] = go3.g[0]; go3.g[2] = go3.g[0];
    gemm_mma_bf16x3<<<dim3(EE / 128, MROWS / 128, 1), 256, GSM_TOTAL>>>(go3, out, 0);
}

// round 14
// speedup vs baseline: 1.1834x; 1.1834x over previous
#include <cuda_runtime.h>
#include <cuda_bf16.h>
#include <math.h>
#include <stdint.h>

// Problem constants
#define LL 2048
#define SS 2048
#define NB 2
#define HH 16
#define DD 64
#define EE 1024
#define BH 32          // NB*HH
#define MROWS 4096     // LL*NB

// ---------------------------------------------------------------------------
// Scratch (device globals; no allocation allowed)
// ---------------------------------------------------------------------------
__device__ __nv_bfloat16 g_qh[(size_t)BH * LL * DD];
__device__ __nv_bfloat16 g_ql[(size_t)BH * LL * DD];
__device__ __nv_bfloat16 g_kh[(size_t)BH * SS * DD];
__device__ __nv_bfloat16 g_kl[(size_t)BH * SS * DD];
__device__ __nv_bfloat16 g_vh[(size_t)BH * SS * DD];
__device__ __nv_bfloat16 g_vl[(size_t)BH * SS * DD];

__device__ __nv_bfloat16 g_a3h[3][(size_t)MROWS * EE];   // q/k/v input splits; [0] reused for attn out
__device__ __nv_bfloat16 g_a3l[3][(size_t)MROWS * EE];
__device__ __nv_bfloat16 g_w3h[4][(size_t)EE * EE];      // Wq, Wk, Wv, Wo transposed splits
__device__ __nv_bfloat16 g_w3l[4][(size_t)EE * EE];

// ---------------------------------------------------------------------------
// Common PTX helpers
// ---------------------------------------------------------------------------
__device__ __forceinline__ uint32_t smem_u32(const void* p) {
    uint32_t a;
    asm("{ .reg .u64 t; cvta.to.shared.u64 t, %1; cvt.u32.u64 %0, t; }"
        : "=r"(a) : "l"(p));
    return a;
}

__device__ __forceinline__ void ldmatrix4(uint32_t* r, uint32_t addr) {
    asm volatile("ldmatrix.sync.aligned.m8n8.x4.shared.b16 {%0,%1,%2,%3}, [%4];"
                 : "=r"(r[0]), "=r"(r[1]), "=r"(r[2]), "=r"(r[3]) : "r"(addr));
}

__device__ __forceinline__ void ldmatrix4t(uint32_t* r, uint32_t addr) {
    asm volatile("ldmatrix.sync.aligned.m8n8.x4.trans.shared.b16 {%0,%1,%2,%3}, [%4];"
                 : "=r"(r[0]), "=r"(r[1]), "=r"(r[2]), "=r"(r[3]) : "r"(addr));
}

__device__ __forceinline__ void mma16816(float* c, const uint32_t* a,
                                         uint32_t b0, uint32_t b1) {
    asm volatile("mma.sync.aligned.m16n8k16.row.col.f32.bf16.bf16.f32 "
                 "{%0,%1,%2,%3}, {%4,%5,%6,%7}, {%8,%9}, {%0,%1,%2,%3};"
                 : "+f"(c[0]), "+f"(c[1]), "+f"(c[2]), "+f"(c[3])
                 : "r"(a[0]), "r"(a[1]), "r"(a[2]), "r"(a[3]), "r"(b0), "r"(b1));
}

// pack two f32 -> bf16x2 (f0 in low half, f1 in high half), RN
__device__ __forceinline__ uint32_t pk_bf16x2(float f0, float f1) {
    uint32_t r;
    asm("cvt.rn.bf16x2.f32 %0, %2, %1;" : "=r"(r) : "f"(f0), "f"(f1));
    return r;
}

#define CP_ASYNC16(dst, src) \
    asm volatile("cp.async.cg.shared.global [%0], [%1], 16;" :: "r"(dst), "l"(src))
#define CP_COMMIT() asm volatile("cp.async.commit_group;" ::: "memory")
#define CP_WAIT1()  asm volatile("cp.async.wait_group 1;" ::: "memory")

// ---------------------------------------------------------------------------
// mma.sync GEMM: C[4096x1024] = X*W via bf16x3 split (K' = 3*1024)
// CTA 128x128, 8 warps (2m x 4n), warp tile 64x32, 3-stage cp.async, 2 CTA/SM.
// blockIdx.z selects the problem instance (merged Q/K/V launch).
// mode 0: fp32 row-major; 1: bf16 hi/lo head-major.
// ---------------------------------------------------------------------------
#define NSTAGE 3
#define NIT 48
#define STAGE_BYTES 32768
#define BOFF 16384
#define GSM_TOTAL (NSTAGE * STAGE_BYTES)

struct GemmArgs {
    const __nv_bfloat16 *ah, *al, *bth, *btl;
    __nv_bfloat16 *dsth, *dstl;
};
struct GemmArgs3 { GemmArgs g[3]; };

__device__ __forceinline__ void load_tile(int it, int buf, int tid, int m0, int n0,
                                          const __nv_bfloat16* __restrict__ Ah,
                                          const __nv_bfloat16* __restrict__ Al,
                                          const __nv_bfloat16* __restrict__ Bth,
                                          const __nv_bfloat16* __restrict__ Btl,
                                          uint32_t sb)
{
    const int term = it >> 4;
    const int kc = (it & 15) << 6;
    const __nv_bfloat16* As = (term == 1) ? Al : Ah;
    const __nv_bfloat16* Bs = (term == 2) ? Btl : Bth;
    const uint32_t abase = sb + buf * STAGE_BYTES;
    const uint32_t bbase = abase + BOFF;
#pragma unroll
    for (int i = 0; i < 8; i++) {
        int g = i * 256 + tid;
        int row = (g >> 3) & 127;
        int c = g & 7;
        const __nv_bfloat16* src;
        uint32_t dst;
        if (g < 1024) {
            src = As + (size_t)(m0 + row) * EE + kc + (c << 3);
            dst = abase + row * 128 + ((c ^ (row & 7)) << 4);
        } else {
            src = Bs + (size_t)(n0 + row) * EE + kc + (c << 3);
            dst = bbase + row * 128 + ((c ^ (row & 7)) << 4);
        }
        CP_ASYNC16(dst, src);
    }
}

__global__ void __launch_bounds__(256, 2) gemm_mma_bf16x3(
    GemmArgs3 A, float* __restrict__ dstf, int mode)
{
    extern __shared__ __align__(1024) char sm[];
    const uint32_t sb = smem_u32(sm);
    const GemmArgs ga = A.g[blockIdx.z];
    const __nv_bfloat16* __restrict__ Ah  = ga.ah;
    const __nv_bfloat16* __restrict__ Al  = ga.al;
    const __nv_bfloat16* __restrict__ Bth = ga.bth;
    const __nv_bfloat16* __restrict__ Btl = ga.btl;
    const int tid = threadIdx.x;
    const int wid = tid >> 5, lane = tid & 31;
    const int wm = wid >> 2;
    const int wn = wid & 3;
    const int m0 = blockIdx.y * 128;
    const int n0 = blockIdx.x * 128;

    float acc[4][4][4];
#pragma unroll
    for (int i = 0; i < 4; i++)
#pragma unroll
        for (int j = 0; j < 4; j++)
#pragma unroll
            for (int k = 0; k < 4; k++) acc[i][j][k] = 0.f;

    load_tile(0, 0, tid, m0, n0, Ah, Al, Bth, Btl, sb);
    CP_COMMIT();
    load_tile(1, 1, tid, m0, n0, Ah, Al, Bth, Btl, sb);
    CP_COMMIT();

    const int a_r = (lane & 7) + ((lane >> 3) & 1) * 8;
    const int a_c8 = lane >> 4;
    const int b_r = (lane & 7) + (lane >> 4) * 8;
    const int b_c8 = (lane >> 3) & 1;

    for (int it = 0; it < NIT; ++it) {
        CP_WAIT1();
        __syncthreads();
        if (it + 2 < NIT)
            load_tile(it + 2, (it + 2) % NSTAGE, tid, m0, n0, Ah, Al, Bth, Btl, sb);
        CP_COMMIT();

        const int buf = it % NSTAGE;
        const uint32_t Ab = sb + buf * STAGE_BYTES;
        const uint32_t Bb = Ab + BOFF;
#pragma unroll
        for (int ks = 0; ks < 4; ks++) {
            const int k0 = ks * 16;
            uint32_t a[4][4];
#pragma unroll
            for (int mt = 0; mt < 4; mt++) {
                int row = wm * 64 + mt * 16 + a_r;
                int col = k0 + 8 * a_c8;
                uint32_t addr = Ab + row * 128 + (((col >> 3) ^ (row & 7)) << 4);
                ldmatrix4(a[mt], addr);
            }
            uint32_t b[2][4];
#pragma unroll
            for (int bt = 0; bt < 2; bt++) {
                int row = wn * 32 + bt * 16 + b_r;
                int col = k0 + 8 * b_c8;
                uint32_t addr = Bb + row * 128 + (((col >> 3) ^ (row & 7)) << 4);
                ldmatrix4(b[bt], addr);
            }
#pragma unroll
            for (int mt = 0; mt < 4; mt++) {
#pragma unroll
                for (int nt = 0; nt < 4; nt++) {
                    uint32_t b0 = b[nt >> 1][(nt & 1) * 2];
                    uint32_t b1 = b[nt >> 1][(nt & 1) * 2 + 1];
                    mma16816(acc[mt][nt], a[mt], b0, b1);
                }
            }
        }
    }

    // Epilogue
#pragma unroll
    for (int mt = 0; mt < 4; mt++) {
#pragma unroll
        for (int nt = 0; nt < 4; nt++) {
            int m = m0 + wm * 64 + mt * 16 + (lane >> 2);
            int n = n0 + wn * 32 + nt * 8 + 2 * (lane & 3);
#pragma unroll
            for (int half = 0; half < 2; half++) {
                int mm = m + half * 8;
                float v0 = acc[mt][nt][half * 2];
                float v1 = acc[mt][nt][half * 2 + 1];
                if (mode == 0) {
                    *(float2*)&dstf[(size_t)mm * EE + n] = make_float2(v0, v1);
                } else {
                    int t = mm >> 1, nb = mm & 1;
                    int h = n >> 6, d = n & 63;
                    size_t idx = ((size_t)((nb * HH + h) * LL + t)) * DD + d;
                    uint32_t hv = pk_bf16x2(v0, v1);
                    float r0 = v0 - __uint_as_float(hv << 16);
                    float r1 = v1 - __uint_as_float(hv & 0xffff0000u);
                    uint32_t lv = pk_bf16x2(r0, r1);
                    *(uint32_t*)&ga.dsth[idx] = hv;
                    *(uint32_t*)&ga.dstl[idx] = lv;
                }
            }
        }
    }
}

// ---------------------------------------------------------------------------
// Conversion kernels (merged over blockIdx.z)
// ---------------------------------------------------------------------------
struct SplitArgs {
    const float* x[3];
    __nv_bfloat16 *h[3], *l[3];
};

__global__ void __launch_bounds__(256) split_kernel(SplitArgs S, int n4)
{
    int i = blockIdx.x * 256 + threadIdx.x;
    if (i >= n4) return;
    const int z = blockIdx.z;
    float4 v = ((const float4*)S.x[z])[i];
    uint32_t h0 = pk_bf16x2(v.x, v.y);
    uint32_t h1 = pk_bf16x2(v.z, v.w);
    float r0 = v.x - __uint_as_float(h0 << 16);
    float r1 = v.y - __uint_as_float(h0 & 0xffff0000u);
    float r2 = v.z - __uint_as_float(h1 << 16);
    float r3 = v.w - __uint_as_float(h1 & 0xffff0000u);
    uint32_t l0 = pk_bf16x2(r0, r1);
    uint32_t l1 = pk_bf16x2(r2, r3);
    *(uint2*)(S.h[z] + 4 * (size_t)i) = make_uint2(h0, h1);
    *(uint2*)(S.l[z] + 4 * (size_t)i) = make_uint2(l0, l1);
}

struct WArgs {
    const float* W[4];
    __nv_bfloat16 *th[4], *tl[4];
};

// W[k][n] -> Wt[n][k] bf16 hi/lo
__global__ void __launch_bounds__(256) wtrans_split(WArgs WA)
{
    __shared__ float t[32][33];
    const int z = blockIdx.z;
    const float* __restrict__ W = WA.W[z];
    const int n0 = blockIdx.x * 32, k0 = blockIdx.y * 32;
    const int tx = threadIdx.x & 31, ty = threadIdx.x >> 5;
#pragma unroll
    for (int j = 0; j < 32; j += 8)
        t[ty + j][tx] = W[(size_t)(k0 + ty + j) * EE + n0 + tx];
    __syncthreads();
#pragma unroll
    for (int j = 0; j < 32; j += 8) {
        float v = t[tx][ty + j];
        __nv_bfloat16 h = __float2bfloat16(v);
        __nv_bfloat16 l = __float2bfloat16(v - __bfloat162float(h));
        WA.th[z][(size_t)(n0 + ty + j) * EE + k0 + tx] = h;
        WA.tl[z][(size_t)(n0 + ty + j) * EE + k0 + tx] = l;
    }
}

// ---------------------------------------------------------------------------
// mma.sync flash attention, 256 threads / 8 warps.
// Each warp owns 16 q-rows x full d=64 (no cross-warp O reduction).
// s-tile 128 per iteration (depth-1 prefetch), processed in four 32-col
// halves; prev/mask loads for each half are HOISTED before that half's QK
// MMAs so the exp path never waits on DRAM.
// QK: bf16x3; PV: bf16x3. No-max softmax.
// smem: Qh 16K | Ql 16K | 2 stages x (Kh|Kl|Vh|Vl 64K)
// ---------------------------------------------------------------------------
#define ASTG(b) (32768 + (b) * 65536)
#define ASM_TOTAL 163840

__global__ void __launch_bounds__(256, 1) attn_mma(
    const __nv_bfloat16* __restrict__ Qh, const __nv_bfloat16* __restrict__ Ql,
    const __nv_bfloat16* __restrict__ Kh, const __nv_bfloat16* __restrict__ Kl,
    const __nv_bfloat16* __restrict__ Vh, const __nv_bfloat16* __restrict__ Vl,
    const float* __restrict__ prev,
    const unsigned char* __restrict__ am, const unsigned char* __restrict__ kpm,
    float* __restrict__ out_logits,
    __nv_bfloat16* __restrict__ oh, __nv_bfloat16* __restrict__ ol)
{
    extern __shared__ __align__(1024) char sm[];
    const uint32_t sb = smem_u32(sm);
    const int tid = threadIdx.x, wid = tid >> 5, lane = tid & 31;
    const int bh = blockIdx.y, nb = bh >> 4, hh = bh & 15;
    const int q0 = blockIdx.x * 128;

    const int a_r = (lane & 7) + ((lane >> 3) & 1) * 8;
    const int a_c8 = lane >> 4;
    const int b_r = (lane & 7) + (lane >> 4) * 8;
    const int b_c8 = (lane >> 3) & 1;

    // Load Q (Qh then Ql): 2048 16B chunks
#pragma unroll
    for (int i = 0; i < 8; i++) {
        int g = i * 256 + tid;
        int arr = g >> 10, local = g & 1023;
        int row = local >> 3, c = local & 7;
        const __nv_bfloat16* src = (arr ? Ql : Qh) +
            ((size_t)bh * LL + q0 + row) * DD + (c << 3);
        uint32_t dst = sb + arr * 16384 + row * 128 + ((c ^ (row & 7)) << 4);
        CP_ASYNC16(dst, src);
    }
    // Stage 0 (Kh, Kl, Vh, Vl): 4096 chunks
#pragma unroll
    for (int i = 0; i < 16; i++) {
        int g = i * 256 + tid;
        int which = g >> 10, local = g & 1023;
        int row = local >> 3, c = local & 7;
        const __nv_bfloat16* base =
            (which == 0) ? Kh : (which == 1) ? Kl : (which == 2) ? Vh : Vl;
        const __nv_bfloat16* src = base + ((size_t)bh * SS + row) * DD + (c << 3);
        uint32_t dst = sb + ASTG(0) + which * 16384 + row * 128 + ((c ^ (row & 7)) << 4);
        CP_ASYNC16(dst, src);
    }
    CP_COMMIT();

    float accO[8][4];
#pragma unroll
    for (int j = 0; j < 8; j++)
#pragma unroll
        for (int k = 0; k < 4; k++) accO[j][k] = 0.f;
    float psum[2] = {0.f, 0.f};

    const int qrow0 = q0 + wid * 16 + (lane >> 2);   // + half*8
    const int colb = 2 * (lane & 3);

    for (int it = 0; it < 16; ++it) {
        const int s0 = it * 128, buf = it & 1;
        if (it + 1 < 16) {
            const int nbuf = (it + 1) & 1, ns0 = (it + 1) * 128;
#pragma unroll
            for (int i = 0; i < 16; i++) {
                int g = i * 256 + tid;
                int which = g >> 10, local = g & 1023;
                int row = local >> 3, c = local & 7;
                const __nv_bfloat16* base =
                    (which == 0) ? Kh : (which == 1) ? Kl : (which == 2) ? Vh : Vl;
                const __nv_bfloat16* src = base +
                    ((size_t)bh * SS + ns0 + row) * DD + (c << 3);
                uint32_t dst = sb + ASTG(nbuf) + which * 16384 + row * 128 +
                               ((c ^ (row & 7)) << 4);
                CP_ASYNC16(dst, src);
            }
        }
        CP_COMMIT();
        CP_WAIT1();
        __syncthreads();

        const uint32_t KB = sb + ASTG(buf);
        const uint32_t VB  = KB + 32768;
        const uint32_t VLB = KB + 49152;

#pragma unroll
        for (int sh = 0; sh < 4; sh++) {        // 32-col half of the 128 s-tile
            // ---- HOISTED prev + mask loads for this half (16 els/lane) ----
            float2 pvv[8];
            uchar2 amv[8], kvv[4];
#pragma unroll
            for (int nt = 0; nt < 4; nt++) {
                const int col = s0 + sh * 32 + nt * 8 + colb;
                kvv[nt] = *(const uchar2*)&kpm[(size_t)nb * SS + col];
#pragma unroll
                for (int half = 0; half < 2; half++) {
                    const int row = qrow0 + half * 8;
                    size_t base = ((size_t)bh * LL + row) * SS + col;
                    pvv[nt * 2 + half] = *(const float2*)&prev[base];
                    amv[nt * 2 + half] = *(const uchar2*)&am[(size_t)row * SS + col];
                }
            }

            // ---- S = Q K^T (3-term split), warp tile m16 x n32 ----
            float accS[4][4];
#pragma unroll
            for (int j = 0; j < 4; j++)
#pragma unroll
                for (int k = 0; k < 4; k++) accS[j][k] = 0.f;

#pragma unroll
            for (int kk = 0; kk < 12; kk++) {
                const int term = kk >> 2, kc = (kk & 3) * 16;
                const uint32_t Ab = sb + (term == 1 ? 16384 : 0);
                const uint32_t Bb = KB + (term == 2 ? 16384 : 0);
                uint32_t a[4];
                {
                    int row = wid * 16 + a_r;
                    int col = kc + 8 * a_c8;
                    ldmatrix4(a, Ab + row * 128 + (((col >> 3) ^ (row & 7)) << 4));
                }
                uint32_t b[2][4];
#pragma unroll
                for (int g = 0; g < 2; g++) {
                    int row = sh * 32 + g * 16 + b_r;
                    int col = kc + 8 * b_c8;
                    ldmatrix4(b[g], Bb + row * 128 + (((col >> 3) ^ (row & 7)) << 4));
                }
#pragma unroll
                for (int nt = 0; nt < 4; nt++)
                    mma16816(accS[nt], a,
                             b[nt >> 1][(nt & 1) * 2], b[nt >> 1][(nt & 1) * 2 + 1]);
            }

            // ---- logits + exp + PV (3-term) per 16-wide k-slice ----
#pragma unroll
            for (int ks = 0; ks < 2; ks++) {
                uint32_t pA[4], pAl[4];
#pragma unroll
                for (int sub = 0; sub < 2; sub++) {
                    const int nt = 2 * ks + sub;
                    const int col = s0 + sh * 32 + nt * 8 + colb;
                    const uchar2 kv2 = kvv[nt];
#pragma unroll
                    for (int half = 0; half < 2; half++) {
                        const int row = qrow0 + half * 8;
                        size_t base = ((size_t)bh * LL + row) * SS + col;
                        float2 pv = pvv[nt * 2 + half];
                        uchar2 av2 = amv[nt * 2 + half];
                        float c0 = accS[nt][half * 2];
                        float c1 = accS[nt][half * 2 + 1];
                        float lg0 = (av2.x | kv2.x) ? -INFINITY : fmaf(c0, 0.125f, pv.x);
                        float lg1 = (av2.y | kv2.y) ? -INFINITY : fmaf(c1, 0.125f, pv.y);
                        __stcs((float2*)&out_logits[base], make_float2(lg0, lg1));
                        float p0 = __expf(lg0), p1 = __expf(lg1);
                        psum[half] += p0 + p1;
                        uint32_t ph = pk_bf16x2(p0, p1);
                        float r0 = p0 - __uint_as_float(ph << 16);
                        float r1 = p1 - __uint_as_float(ph & 0xffff0000u);
                        pA[sub * 2 + half]  = ph;
                        pAl[sub * 2 + half] = pk_bf16x2(r0, r1);
                    }
                }
                const int vrow = sh * 32 + ks * 16 + a_r;
                uint32_t vb[4][4];
#pragma unroll
                for (int dg = 0; dg < 4; dg++) {
                    int chunk = dg * 2 + (lane >> 4);
                    ldmatrix4t(vb[dg], VB + vrow * 128 + ((chunk ^ (vrow & 7)) << 4));
                }
#pragma unroll
                for (int dn = 0; dn < 8; dn++) {
                    uint32_t b0 = vb[dn >> 1][(dn & 1) * 2];
                    uint32_t b1 = vb[dn >> 1][(dn & 1) * 2 + 1];
                    mma16816(accO[dn], pA, b0, b1);
                    mma16816(accO[dn], pAl, b0, b1);
                }
                uint32_t vbl[4][4];
#pragma unroll
                for (int dg = 0; dg < 4; dg++) {
                    int chunk = dg * 2 + (lane >> 4);
                    ldmatrix4t(vbl[dg], VLB + vrow * 128 + ((chunk ^ (vrow & 7)) << 4));
                }
#pragma unroll
                for (int dn = 0; dn < 8; dn++)
                    mma16816(accO[dn], pA,
                             vbl[dn >> 1][(dn & 1) * 2], vbl[dn >> 1][(dn & 1) * 2 + 1]);
            }
        }
        __syncthreads();
    }

    // ---- epilogue: in-warp row-sum, normalize, split-write (warp-private) ----
    float inv[2];
#pragma unroll
    for (int half = 0; half < 2; half++) {
        float v = psum[half];
        v += __shfl_xor_sync(0xffffffffu, v, 1);
        v += __shfl_xor_sync(0xffffffffu, v, 2);
        inv[half] = 1.f / v;
    }
#pragma unroll
    for (int dn = 0; dn < 8; dn++) {
#pragma unroll
        for (int half = 0; half < 2; half++) {
            int rl = wid * 16 + (lane >> 2) + half * 8;
            int col = dn * 8 + colb;
            float o0 = accO[dn][half * 2] * inv[half];
            float o1 = accO[dn][half * 2 + 1] * inv[half];
            size_t r = (size_t)(q0 + rl) * NB + nb;
            size_t cg = (size_t)hh * 64 + col;
            uint32_t hv = pk_bf16x2(o0, o1);
            float r0 = o0 - __uint_as_float(hv << 16);
            float r1 = o1 - __uint_as_float(hv & 0xffff0000u);
            uint32_t lv = pk_bf16x2(r0, r1);
            *(uint32_t*)&oh[r * EE + cg] = hv;
            *(uint32_t*)&ol[r * EE + cg] = lv;
        }
    }
}

// ---------------------------------------------------------------------------
extern "C" void kernel_launch(void* const* d_in, const int* in_sizes, int n_in,
                              void* d_out, int out_size)
{
    const float* query = (const float*)d_in[0];
    const float* key   = (const float*)d_in[1];
    const float* value = (const float*)d_in[2];
    const float* prev  = (const float*)d_in[3];
    const unsigned char* kpm = (const unsigned char*)d_in[4];
    const unsigned char* am  = (const unsigned char*)d_in[5];
    const float* Wq = (const float*)d_in[6];
    const float* Wk = (const float*)d_in[7];
    const float* Wv = (const float*)d_in[8];
    const float* Wo = (const float*)d_in[9];

    float* out = (float*)d_out;
    float* out_logits = out + (size_t)LL * NB * EE;

    __nv_bfloat16 *qh, *ql, *kh, *kl, *vh, *vl;
    __nv_bfloat16 *a3h, *a3l, *w3h, *w3l;
    cudaGetSymbolAddress((void**)&qh, g_qh);
    cudaGetSymbolAddress((void**)&ql, g_ql);
    cudaGetSymbolAddress((void**)&kh, g_kh);
    cudaGetSymbolAddress((void**)&kl, g_kl);
    cudaGetSymbolAddress((void**)&vh, g_vh);
    cudaGetSymbolAddress((void**)&vl, g_vl);
    cudaGetSymbolAddress((void**)&a3h, g_a3h);
    cudaGetSymbolAddress((void**)&a3l, g_a3l);
    cudaGetSymbolAddress((void**)&w3h, g_w3h);
    cudaGetSymbolAddress((void**)&w3l, g_w3l);

    const size_t ASZ = (size_t)MROWS * EE;
    const size_t WSZ = (size_t)EE * EE;

    cudaFuncSetAttribute(gemm_mma_bf16x3,
                         cudaFuncAttributeMaxDynamicSharedMemorySize, GSM_TOTAL);
    cudaFuncSetAttribute(attn_mma,
                         cudaFuncAttributeMaxDynamicSharedMemorySize, ASM_TOTAL);

    const int nsplit4 = MROWS * EE / 4;

    // 1) Transpose+split all 4 weight matrices (z = 4)
    WArgs wa;
    wa.W[0] = Wq; wa.W[1] = Wk; wa.W[2] = Wv; wa.W[3] = Wo;
    for (int z = 0; z < 4; z++) { wa.th[z] = w3h + z * WSZ; wa.tl[z] = w3l + z * WSZ; }
    wtrans_split<<<dim3(EE / 32, EE / 32, 4), 256>>>(wa);

    // 2) Split all 3 inputs (z = 3)
    SplitArgs sa;
    sa.x[0] = query; sa.x[1] = key; sa.x[2] = value;
    for (int z = 0; z < 3; z++) { sa.h[z] = a3h + z * ASZ; sa.l[z] = a3l + z * ASZ; }
    split_kernel<<<dim3((nsplit4 + 255) / 256, 1, 3), 256>>>(sa, nsplit4);

    // 3) Q/K/V projections in one launch (z = 3), bf16 hi/lo head-major out
    GemmArgs3 g3;
    __nv_bfloat16* dh[3] = {qh, kh, vh};
    __nv_bfloat16* dl[3] = {ql, kl, vl};
    for (int z = 0; z < 3; z++) {
        g3.g[z].ah = a3h + z * ASZ;  g3.g[z].al = a3l + z * ASZ;
        g3.g[z].bth = w3h + z * WSZ; g3.g[z].btl = w3l + z * WSZ;
        g3.g[z].dsth = dh[z];        g3.g[z].dstl = dl[z];
    }
    gemm_mma_bf16x3<<<dim3(EE / 128, MROWS / 128, 3), 256, GSM_TOTAL>>>(g3, nullptr, 1);

    // 4) Attention (writes logits + attn-out split into a3h[0]/a3l[0])
    attn_mma<<<dim3(LL / 128, BH), 256, ASM_TOTAL>>>(qh, ql, kh, kl, vh, vl,
                                                     prev, am, kpm,
                                                     out_logits, a3h, a3l);

    // 5) Output projection (fp32 row-major)
    GemmArgs3 go3;
    go3.g[0].ah = a3h;               go3.g[0].al = a3l;
    go3.g[0].bth = w3h + 3 * WSZ;    go3.g[0].btl = w3l + 3 * WSZ;
    go3.g[0].dsth = nullptr;         go3.g[0].dstl = nullptr;
    go3.g[1] = go3.g[0]; go3.g[2] = go3.g[0];
    gemm_mma_bf16x3<<<dim3(EE / 128, MROWS / 128, 1), 256, GSM_TOTAL>>>(go3, out, 0);
}